// round 3
// baseline (speedup 1.0000x reference)
#include <cuda_runtime.h>
#include <cstdint>

#define BB    8
#define NN1   16384
#define NN2   4096
#define COUT  128
#define CHUNK 2048

// Scratch (device globals; no allocation allowed)
__device__ float g_f0[(size_t)BB * COUT * NN2];      // layer0 output [B][128][N2]
__device__ float g_ft[(size_t)BB * NN2 * COUT];      // layer1 output transposed [B][N2][128]

// ---------------------------------------------------------------------------
// Fused 1x1 conv + BN + ReLU.  X:[B][CIN][N2]  W:[128][CIN]
// Block = 256 threads computes a [128 cout x 32 n] tile, 4x4 register blocking.
// TRANS=false: out[b][cout][n];  TRANS=true: out[b][n][cout] (for gather)
// ---------------------------------------------------------------------------
template<int CIN, bool TRANS>
__global__ void __launch_bounds__(256)
conv_bn_relu_kernel(const float* __restrict__ X,
                    const float* __restrict__ W,
                    const float* __restrict__ bias,
                    const float* __restrict__ gamma,
                    const float* __restrict__ beta,
                    const float* __restrict__ mean,
                    const float* __restrict__ var,
                    float* __restrict__ out)
{
    __shared__ __align__(16) float Ws[32][132];   // [c][cout], padded (16B-aligned rows)
    __shared__ __align__(16) float Xs[32][36];    // [c][n],    padded (16B-aligned rows)

    const int t    = threadIdx.x;
    const int b    = blockIdx.y;
    const int n0   = blockIdx.x * 32;
    const int colb = (t & 7) * 4;     // 4 consecutive n columns
    const int rowb = (t >> 3) * 4;    // 4 consecutive cout rows

    float acc[4][4];
#pragma unroll
    for (int i = 0; i < 4; i++)
#pragma unroll
        for (int j = 0; j < 4; j++) acc[i][j] = 0.f;

    const float* Xb = X + (size_t)b * CIN * NN2;

    for (int c0 = 0; c0 < CIN; c0 += 32) {
        // stage W tile [32 c x 128 cout]
#pragma unroll
        for (int k = 0; k < 16; k++) {
            int idx = t + k * 256;
            int r = idx >> 5, c = idx & 31;
            Ws[c][r] = W[r * CIN + c0 + c];
        }
        // stage X tile [32 c x 32 n]
#pragma unroll
        for (int k = 0; k < 4; k++) {
            int idx = t + k * 256;
            int cc = idx >> 5, nn = idx & 31;
            Xs[cc][nn] = Xb[(size_t)(c0 + cc) * NN2 + n0 + nn];
        }
        __syncthreads();

#pragma unroll
        for (int cc = 0; cc < 32; cc++) {
            float4 xv = *(const float4*)&Xs[cc][colb];
            float4 wv = *(const float4*)&Ws[cc][rowb];
            acc[0][0] = fmaf(wv.x, xv.x, acc[0][0]);
            acc[0][1] = fmaf(wv.x, xv.y, acc[0][1]);
            acc[0][2] = fmaf(wv.x, xv.z, acc[0][2]);
            acc[0][3] = fmaf(wv.x, xv.w, acc[0][3]);
            acc[1][0] = fmaf(wv.y, xv.x, acc[1][0]);
            acc[1][1] = fmaf(wv.y, xv.y, acc[1][1]);
            acc[1][2] = fmaf(wv.y, xv.z, acc[1][2]);
            acc[1][3] = fmaf(wv.y, xv.w, acc[1][3]);
            acc[2][0] = fmaf(wv.z, xv.x, acc[2][0]);
            acc[2][1] = fmaf(wv.z, xv.y, acc[2][1]);
            acc[2][2] = fmaf(wv.z, xv.z, acc[2][2]);
            acc[2][3] = fmaf(wv.z, xv.w, acc[2][3]);
            acc[3][0] = fmaf(wv.w, xv.x, acc[3][0]);
            acc[3][1] = fmaf(wv.w, xv.y, acc[3][1]);
            acc[3][2] = fmaf(wv.w, xv.z, acc[3][2]);
            acc[3][3] = fmaf(wv.w, xv.w, acc[3][3]);
        }
        __syncthreads();
    }

    // BN + ReLU epilogue
    float val[4][4];
#pragma unroll
    for (int i = 0; i < 4; i++) {
        int r = rowb + i;
        float sc = gamma[r] * rsqrtf(var[r] + 1e-5f);
        float sh = fmaf(bias[r] - mean[r], sc, beta[r]);
#pragma unroll
        for (int j = 0; j < 4; j++)
            val[i][j] = fmaxf(fmaf(acc[i][j], sc, sh), 0.f);
    }

    if (!TRANS) {
#pragma unroll
        for (int i = 0; i < 4; i++) {
            float4 v = make_float4(val[i][0], val[i][1], val[i][2], val[i][3]);
            *(float4*)&out[((size_t)b * COUT + rowb + i) * NN2 + n0 + colb] = v;
        }
    } else {
#pragma unroll
        for (int j = 0; j < 4; j++) {
            float4 v = make_float4(val[0][j], val[1][j], val[2][j], val[3][j]);
            *(float4*)&out[((size_t)b * NN2 + n0 + colb + j) * COUT + rowb] = v;
        }
    }
}

// ---------------------------------------------------------------------------
// 3-NN + weighted interpolation.
// One thread per query point; p2 (x,y,z,|p|^2) staged in smem (2 chunks of
// 2048 float4 = 32KB).  Selection key s = |p2|^2 - 2*p1.p2 (drop the constant
// |p1|^2 during the scan: same ordering, re-added for the weights, matching
// the reference's expansion-trick distances).
// ---------------------------------------------------------------------------
__global__ void __launch_bounds__(256)
knn_interp_kernel(const float* __restrict__ p1,
                  const float* __restrict__ p2,
                  const float* __restrict__ ft,   // [B][N2][128]
                  float* __restrict__ out)        // [B][128][N1]
{
    __shared__ __align__(16) float4 sp[CHUNK];

    const int t = threadIdx.x;
    const int b = blockIdx.y;
    const int n = blockIdx.x * 256 + t;

    const float* pp = p1 + ((size_t)b * NN1 + n) * 3;
    const float px = pp[0], py = pp[1], pz = pp[2];
    const float mx = -2.f * px, my = -2.f * py, mz = -2.f * pz;
    const float c1 = px * px + py * py + pz * pz;

    const float INF = __int_as_float(0x7f800000);
    float d0 = INF, d1 = INF, d2 = INF;
    int   i0 = 0,   i1 = 0,   i2 = 0;

    const float* p2b = p2 + (size_t)b * NN2 * 3;

    for (int base = 0; base < NN2; base += CHUNK) {
        for (int k = t; k < CHUNK; k += 256) {
            const float* q = p2b + (size_t)(base + k) * 3;
            float x = q[0], y = q[1], z = q[2];
            sp[k] = make_float4(x, y, z, fmaf(x, x, fmaf(y, y, z * z)));
        }
        __syncthreads();

#pragma unroll 4
        for (int k = 0; k < CHUNK; k++) {
            float4 q = sp[k];
            float s = fmaf(q.x, mx, fmaf(q.y, my, fmaf(q.z, mz, q.w)));
            int id = base + k;
            bool b2 = s < d2, b1 = s < d1, b0 = s < d0;
            float nd2 = b1 ? d1 : (b2 ? s : d2);
            int   ni2 = b1 ? i1 : (b2 ? id : i2);
            float nd1 = b0 ? d0 : (b1 ? s : d1);
            int   ni1 = b0 ? i0 : (b1 ? id : i1);
            d0 = b0 ? s : d0;  i0 = b0 ? id : i0;
            d1 = nd1; i1 = ni1;
            d2 = nd2; i2 = ni2;
        }
        __syncthreads();
    }

    // weights (reference: recip = 1/(d2 + 1e-8), normalized)
    float dd0 = d0 + c1, dd1 = d1 + c1, dd2 = d2 + c1;
    float r0 = 1.f / (dd0 + 1e-8f);
    float r1 = 1.f / (dd1 + 1e-8f);
    float r2 = 1.f / (dd2 + 1e-8f);
    float inv = 1.f / (r0 + r1 + r2);
    float w0 = r0 * inv, w1 = r1 * inv, w2 = r2 * inv;

    const float4* f0 = (const float4*)(ft + ((size_t)b * NN2 + i0) * COUT);
    const float4* f1 = (const float4*)(ft + ((size_t)b * NN2 + i1) * COUT);
    const float4* f2 = (const float4*)(ft + ((size_t)b * NN2 + i2) * COUT);
    float* ob = out + (size_t)b * COUT * NN1 + n;

#pragma unroll 4
    for (int j = 0; j < COUT / 4; j++) {
        float4 a = f0[j], c = f1[j], e = f2[j];
        float vx = w0 * a.x + w1 * c.x + w2 * e.x;
        float vy = w0 * a.y + w1 * c.y + w2 * e.y;
        float vz = w0 * a.z + w1 * c.z + w2 * e.z;
        float vw = w0 * a.w + w1 * c.w + w2 * e.w;
        ob[(size_t)(4 * j + 0) * NN1] = vx;
        ob[(size_t)(4 * j + 1) * NN1] = vy;
        ob[(size_t)(4 * j + 2) * NN1] = vz;
        ob[(size_t)(4 * j + 3) * NN1] = vw;
    }
}

// ---------------------------------------------------------------------------
extern "C" void kernel_launch(void* const* d_in, const int* in_sizes, int n_in,
                              void* d_out, int out_size)
{
    const float* p1 = (const float*)d_in[0];
    const float* p2 = (const float*)d_in[1];
    const float* f2 = (const float*)d_in[2];
    const float* W0 = (const float*)d_in[3];
    const float* b0 = (const float*)d_in[4];
    const float* g0 = (const float*)d_in[5];
    const float* be0 = (const float*)d_in[6];
    const float* m0 = (const float*)d_in[7];
    const float* v0 = (const float*)d_in[8];
    const float* W1 = (const float*)d_in[9];
    const float* b1 = (const float*)d_in[10];
    const float* g1 = (const float*)d_in[11];
    const float* be1 = (const float*)d_in[12];
    const float* m1 = (const float*)d_in[13];
    const float* v1 = (const float*)d_in[14];

    float* f0p = nullptr;
    float* ftp = nullptr;
    cudaGetSymbolAddress((void**)&f0p, g_f0);
    cudaGetSymbolAddress((void**)&ftp, g_ft);

    dim3 ggrid(NN2 / 32, BB);
    conv_bn_relu_kernel<256, false><<<ggrid, 256>>>(f2, W0, b0, g0, be0, m0, v0, f0p);
    conv_bn_relu_kernel<128, true ><<<ggrid, 256>>>(f0p, W1, b1, g1, be1, m1, v1, ftp);

    dim3 kgrid(NN1 / 256, BB);
    knn_interp_kernel<<<kgrid, 256>>>(p1, p2, ftp, (float*)d_out);
}

// round 7
// speedup vs baseline: 1.0764x; 1.0764x over previous
#include <cuda_runtime.h>
#include <cstdint>

#define BB    8
#define NN1   16384
#define NN2   4096
#define COUT  128
#define CHUNK 2048

typedef unsigned long long ull;

// Scratch (device globals; no allocation allowed)
__device__ float g_f0[(size_t)BB * COUT * NN2];      // layer0 output [B][128][N2]
__device__ float g_ft[(size_t)BB * NN2 * COUT];      // layer1 output transposed [B][N2][128]

// ---------------------------------------------------------------------------
// packed f32x2 helpers
// ---------------------------------------------------------------------------
__device__ __forceinline__ void fma2(ull& d, ull a, ull b, ull c) {
    asm("fma.rn.f32x2 %0, %1, %2, %3;" : "=l"(d) : "l"(a), "l"(b), "l"(c));
}
__device__ __forceinline__ ull pack2(float lo, float hi) {
    ull r; asm("mov.b64 %0, {%1, %2};" : "=l"(r) : "f"(lo), "f"(hi)); return r;
}
__device__ __forceinline__ float2 unpack2(ull v) {
    float2 r; asm("mov.b64 {%0, %1}, %2;" : "=f"(r.x), "=f"(r.y) : "l"(v)); return r;
}
union F4U { float4 f; ull u[2]; };

// ---------------------------------------------------------------------------
// Fused 1x1 conv + BN + ReLU.  X:[B][CIN][N2]  W:[128][CIN]
// Block = 256 threads computes a [128 cout x 64 n] tile.
// Thread tile: 4 cout x 8 n, accumulated as 16 packed f32x2 (over n pairs).
// TRANS=false: out[b][cout][n];  TRANS=true: out[b][n][cout]
// ---------------------------------------------------------------------------
template<int CIN, bool TRANS>
__global__ void __launch_bounds__(256)
conv_bn_relu_kernel(const float* __restrict__ X,
                    const float* __restrict__ W,
                    const float* __restrict__ bias,
                    const float* __restrict__ gamma,
                    const float* __restrict__ beta,
                    const float* __restrict__ mean,
                    const float* __restrict__ var,
                    float* __restrict__ out)
{
    __shared__ __align__(16) float Ws[32][132];   // [k][cout], padded
    __shared__ __align__(16) float Xs[32][68];    // [k][n],    padded

    const int t    = threadIdx.x;
    const int b    = blockIdx.y;
    const int n0   = blockIdx.x * 64;
    const int colb = (t & 7) * 8;     // 8 consecutive n columns
    const int rowb = (t >> 3) * 4;    // 4 consecutive cout rows

    ull acc[4][4];                    // [cout][n-pair]
#pragma unroll
    for (int i = 0; i < 4; i++)
#pragma unroll
        for (int j = 0; j < 4; j++) acc[i][j] = pack2(0.f, 0.f);

    const float* Xb = X + (size_t)b * CIN * NN2;

    for (int c0 = 0; c0 < CIN; c0 += 32) {
        // stage W tile [32 k x 128 cout]
#pragma unroll
        for (int k = 0; k < 16; k++) {
            int idx = t + k * 256;
            int r = idx >> 5, c = idx & 31;
            Ws[c][r] = W[r * CIN + c0 + c];
        }
        // stage X tile [32 k x 64 n]
#pragma unroll
        for (int k = 0; k < 8; k++) {
            int idx = t + k * 256;
            int cc = idx >> 6, nn = idx & 63;
            Xs[cc][nn] = Xb[(size_t)(c0 + cc) * NN2 + n0 + nn];
        }
        __syncthreads();

#pragma unroll
        for (int cc = 0; cc < 32; cc++) {
            F4U xlo, xhi;
            xlo.f = *(const float4*)&Xs[cc][colb];
            xhi.f = *(const float4*)&Xs[cc][colb + 4];
            float4 wv = *(const float4*)&Ws[cc][rowb];
            ull xp0 = xlo.u[0], xp1 = xlo.u[1], xp2 = xhi.u[0], xp3 = xhi.u[1];
            ull w0 = pack2(wv.x, wv.x);
            ull w1 = pack2(wv.y, wv.y);
            ull w2 = pack2(wv.z, wv.z);
            ull w3 = pack2(wv.w, wv.w);
            fma2(acc[0][0], xp0, w0, acc[0][0]);
            fma2(acc[0][1], xp1, w0, acc[0][1]);
            fma2(acc[0][2], xp2, w0, acc[0][2]);
            fma2(acc[0][3], xp3, w0, acc[0][3]);
            fma2(acc[1][0], xp0, w1, acc[1][0]);
            fma2(acc[1][1], xp1, w1, acc[1][1]);
            fma2(acc[1][2], xp2, w1, acc[1][2]);
            fma2(acc[1][3], xp3, w1, acc[1][3]);
            fma2(acc[2][0], xp0, w2, acc[2][0]);
            fma2(acc[2][1], xp1, w2, acc[2][1]);
            fma2(acc[2][2], xp2, w2, acc[2][2]);
            fma2(acc[2][3], xp3, w2, acc[2][3]);
            fma2(acc[3][0], xp0, w3, acc[3][0]);
            fma2(acc[3][1], xp1, w3, acc[3][1]);
            fma2(acc[3][2], xp2, w3, acc[3][2]);
            fma2(acc[3][3], xp3, w3, acc[3][3]);
        }
        __syncthreads();
    }

    // BN + ReLU epilogue
    float val[4][8];
#pragma unroll
    for (int i = 0; i < 4; i++) {
        int r = rowb + i;
        float sc = gamma[r] * rsqrtf(var[r] + 1e-5f);
        float sh = fmaf(bias[r] - mean[r], sc, beta[r]);
#pragma unroll
        for (int j = 0; j < 4; j++) {
            float2 p = unpack2(acc[i][j]);
            val[i][2 * j + 0] = fmaxf(fmaf(p.x, sc, sh), 0.f);
            val[i][2 * j + 1] = fmaxf(fmaf(p.y, sc, sh), 0.f);
        }
    }

    if (!TRANS) {
#pragma unroll
        for (int i = 0; i < 4; i++) {
            float* o = &out[((size_t)b * COUT + rowb + i) * NN2 + n0 + colb];
            *(float4*)&o[0] = make_float4(val[i][0], val[i][1], val[i][2], val[i][3]);
            *(float4*)&o[4] = make_float4(val[i][4], val[i][5], val[i][6], val[i][7]);
        }
    } else {
#pragma unroll
        for (int j = 0; j < 8; j++) {
            float4 v = make_float4(val[0][j], val[1][j], val[2][j], val[3][j]);
            *(float4*)&out[((size_t)b * NN2 + n0 + colb + j) * COUT + rowb] = v;
        }
    }
}

// ---------------------------------------------------------------------------
// branchless top-3 insert (ascending d0<=d1<=d2); correct even if s>=d2
// ---------------------------------------------------------------------------
__device__ __forceinline__ void ins3(float s, int id,
                                     float& d0, float& d1, float& d2,
                                     int& i0, int& i1, int& i2)
{
    bool c2 = s < d2, c1 = s < d1, c0 = s < d0;
    float nd2 = c1 ? d1 : (c2 ? s : d2);
    int   ni2 = c1 ? i1 : (c2 ? id : i2);
    float nd1 = c0 ? d0 : (c1 ? s : d1);
    int   ni1 = c0 ? i0 : (c1 ? id : i1);
    d0 = c0 ? s : d0;  i0 = c0 ? id : i0;
    d1 = nd1; i1 = ni1;
    d2 = nd2; i2 = ni2;
}

// ---------------------------------------------------------------------------
// 3-NN + weighted interpolation.
// One thread per query point.  p2 staged in smem as SoA (x,y,z,|p|^2).
// Selection key s = |p2|^2 - 2*p1.p2 (constant |p1|^2 dropped during the
// scan, re-added for the weights -> identical to reference expansion trick).
// Fast path per 4 candidates: 4 LDS.128 + 6 FFMA2 + min-tournament + skip.
// ---------------------------------------------------------------------------
__global__ void __launch_bounds__(256)
knn_interp_kernel(const float* __restrict__ p1,
                  const float* __restrict__ p2,
                  const float* __restrict__ ft,   // [B][N2][128]
                  float* __restrict__ out)        // [B][128][N1]
{
    __shared__ __align__(16) float sx[CHUNK];
    __shared__ __align__(16) float sy[CHUNK];
    __shared__ __align__(16) float sz[CHUNK];
    __shared__ __align__(16) float sw[CHUNK];

    const int t = threadIdx.x;
    const int b = blockIdx.y;
    const int n = blockIdx.x * 256 + t;

    const float* pp = p1 + ((size_t)b * NN1 + n) * 3;
    const float px = pp[0], py = pp[1], pz = pp[2];
    const ull MX2 = pack2(-2.f * px, -2.f * px);
    const ull MY2 = pack2(-2.f * py, -2.f * py);
    const ull MZ2 = pack2(-2.f * pz, -2.f * pz);
    const float c1 = px * px + py * py + pz * pz;

    const float INF = __int_as_float(0x7f800000);
    float d0 = INF, d1 = INF, d2 = INF;
    int   i0 = 0,   i1 = 0,   i2 = 0;

    const float* p2b = p2 + (size_t)b * NN2 * 3;

    for (int base = 0; base < NN2; base += CHUNK) {
        for (int k = t; k < CHUNK; k += 256) {
            const float* q = p2b + (size_t)(base + k) * 3;
            float x = q[0], y = q[1], z = q[2];
            sx[k] = x; sy[k] = y; sz[k] = z;
            sw[k] = fmaf(x, x, fmaf(y, y, z * z));
        }
        __syncthreads();

#pragma unroll 2
        for (int k = 0; k < CHUNK; k += 4) {
            F4U xq, yq, zq, wq;
            xq.f = *(const float4*)&sx[k];
            yq.f = *(const float4*)&sy[k];
            zq.f = *(const float4*)&sz[k];
            wq.f = *(const float4*)&sw[k];

            ull s01 = wq.u[0], s23 = wq.u[1];
            fma2(s01, xq.u[0], MX2, s01);
            fma2(s01, yq.u[0], MY2, s01);
            fma2(s01, zq.u[0], MZ2, s01);
            fma2(s23, xq.u[1], MX2, s23);
            fma2(s23, yq.u[1], MY2, s23);
            fma2(s23, zq.u[1], MZ2, s23);

            float2 a = unpack2(s01);
            float2 c = unpack2(s23);
            float m = fminf(fminf(a.x, a.y), fminf(c.x, c.y));
            if (m < d2) {
                int id = base + k;
                if (a.x < d2) ins3(a.x, id + 0, d0, d1, d2, i0, i1, i2);
                if (a.y < d2) ins3(a.y, id + 1, d0, d1, d2, i0, i1, i2);
                if (c.x < d2) ins3(c.x, id + 2, d0, d1, d2, i0, i1, i2);
                if (c.y < d2) ins3(c.y, id + 3, d0, d1, d2, i0, i1, i2);
            }
        }
        __syncthreads();
    }

    // weights (reference: recip = 1/(d2 + 1e-8), normalized)
    float r0 = 1.f / (d0 + c1 + 1e-8f);
    float r1 = 1.f / (d1 + c1 + 1e-8f);
    float r2 = 1.f / (d2 + c1 + 1e-8f);
    float inv = 1.f / (r0 + r1 + r2);
    float w0 = r0 * inv, w1 = r1 * inv, w2 = r2 * inv;

    const float4* f0 = (const float4*)(ft + ((size_t)b * NN2 + i0) * COUT);
    const float4* f1 = (const float4*)(ft + ((size_t)b * NN2 + i1) * COUT);
    const float4* f2 = (const float4*)(ft + ((size_t)b * NN2 + i2) * COUT);
    float* ob = out + (size_t)b * COUT * NN1 + n;

#pragma unroll 4
    for (int j = 0; j < COUT / 4; j++) {
        float4 a = f0[j], c = f1[j], e = f2[j];
        float vx = w0 * a.x + w1 * c.x + w2 * e.x;
        float vy = w0 * a.y + w1 * c.y + w2 * e.y;
        float vz = w0 * a.z + w1 * c.z + w2 * e.z;
        float vw = w0 * a.w + w1 * c.w + w2 * e.w;
        ob[(size_t)(4 * j + 0) * NN1] = vx;
        ob[(size_t)(4 * j + 1) * NN1] = vy;
        ob[(size_t)(4 * j + 2) * NN1] = vz;
        ob[(size_t)(4 * j + 3) * NN1] = vw;
    }
}

// ---------------------------------------------------------------------------
extern "C" void kernel_launch(void* const* d_in, const int* in_sizes, int n_in,
                              void* d_out, int out_size)
{
    const float* p1 = (const float*)d_in[0];
    const float* p2 = (const float*)d_in[1];
    const float* f2 = (const float*)d_in[2];
    const float* W0 = (const float*)d_in[3];
    const float* b0 = (const float*)d_in[4];
    const float* g0 = (const float*)d_in[5];
    const float* be0 = (const float*)d_in[6];
    const float* m0 = (const float*)d_in[7];
    const float* v0 = (const float*)d_in[8];
    const float* W1 = (const float*)d_in[9];
    const float* b1 = (const float*)d_in[10];
    const float* g1 = (const float*)d_in[11];
    const float* be1 = (const float*)d_in[12];
    const float* m1 = (const float*)d_in[13];
    const float* v1 = (const float*)d_in[14];

    float* f0p = nullptr;
    float* ftp = nullptr;
    cudaGetSymbolAddress((void**)&f0p, g_f0);
    cudaGetSymbolAddress((void**)&ftp, g_ft);

    dim3 ggrid(NN2 / 64, BB);
    conv_bn_relu_kernel<256, false><<<ggrid, 256>>>(f2, W0, b0, g0, be0, m0, v0, f0p);
    conv_bn_relu_kernel<128, true ><<<ggrid, 256>>>(f0p, W1, b1, g1, be1, m1, v1, ftp);

    dim3 kgrid(NN1 / 256, BB);
    knn_interp_kernel<<<kgrid, 256>>>(p1, p2, ftp, (float*)d_out);
}

// round 8
// speedup vs baseline: 1.6689x; 1.5505x over previous
#include <cuda_runtime.h>
#include <cstdint>

#define BB    8
#define NN1   16384
#define NN2   4096
#define COUT  128
#define CHUNK 2048

typedef unsigned long long ull;

// Scratch (device globals; no allocation allowed)
__device__ float g_f0[(size_t)BB * COUT * NN2];      // layer0 output [B][128][N2]
__device__ float g_ft[(size_t)BB * NN2 * COUT];      // layer1 output transposed [B][N2][128]

// ---------------------------------------------------------------------------
// packed f32x2 helpers (used only in the kNN distance evaluation)
// ---------------------------------------------------------------------------
__device__ __forceinline__ void fma2(ull& d, ull a, ull b, ull c) {
    asm("fma.rn.f32x2 %0, %1, %2, %3;" : "=l"(d) : "l"(a), "l"(b), "l"(c));
}
__device__ __forceinline__ ull pack2(float lo, float hi) {
    ull r; asm("mov.b64 %0, {%1, %2};" : "=l"(r) : "f"(lo), "f"(hi)); return r;
}
__device__ __forceinline__ float2 unpack2(ull v) {
    float2 r; asm("mov.b64 {%0, %1}, %2;" : "=f"(r.x), "=f"(r.y) : "l"(v)); return r;
}
union F4U { float4 f; ull u[2]; };

// ---------------------------------------------------------------------------
// Fused 1x1 conv + BN + ReLU.  X:[B][CIN][N2]  W:[128][CIN]
// Block = 256 threads computes a [128 cout x 64 n] tile.
// Thread tile: 4 cout x 8 n, SCALAR FFMA accumulation (32 FFMA / 3 LDS.128).
// TRANS=false: out[b][cout][n];  TRANS=true: out[b][n][cout]
// ---------------------------------------------------------------------------
template<int CIN, bool TRANS>
__global__ void __launch_bounds__(256)
conv_bn_relu_kernel(const float* __restrict__ X,
                    const float* __restrict__ W,
                    const float* __restrict__ bias,
                    const float* __restrict__ gamma,
                    const float* __restrict__ beta,
                    const float* __restrict__ mean,
                    const float* __restrict__ var,
                    float* __restrict__ out)
{
    __shared__ __align__(16) float Ws[32][132];   // [k][cout], padded
    __shared__ __align__(16) float Xs[32][68];    // [k][n],    padded

    const int t    = threadIdx.x;
    const int b    = blockIdx.y;
    const int n0   = blockIdx.x * 64;
    const int colb = (t & 7) * 8;     // 8 consecutive n columns
    const int rowb = (t >> 3) * 4;    // 4 consecutive cout rows

    float acc[4][8];
#pragma unroll
    for (int i = 0; i < 4; i++)
#pragma unroll
        for (int j = 0; j < 8; j++) acc[i][j] = 0.f;

    const float* Xb = X + (size_t)b * CIN * NN2;

    for (int c0 = 0; c0 < CIN; c0 += 32) {
        // stage W tile [32 k x 128 cout]
#pragma unroll
        for (int k = 0; k < 16; k++) {
            int idx = t + k * 256;
            int r = idx >> 5, c = idx & 31;
            Ws[c][r] = W[r * CIN + c0 + c];
        }
        // stage X tile [32 k x 64 n]
#pragma unroll
        for (int k = 0; k < 8; k++) {
            int idx = t + k * 256;
            int cc = idx >> 6, nn = idx & 63;
            Xs[cc][nn] = Xb[(size_t)(c0 + cc) * NN2 + n0 + nn];
        }
        __syncthreads();

#pragma unroll
        for (int cc = 0; cc < 32; cc++) {
            float4 xlo = *(const float4*)&Xs[cc][colb];
            float4 xhi = *(const float4*)&Xs[cc][colb + 4];
            float4 wv  = *(const float4*)&Ws[cc][rowb];
            float xr[8] = {xlo.x, xlo.y, xlo.z, xlo.w, xhi.x, xhi.y, xhi.z, xhi.w};
            float wr[4] = {wv.x, wv.y, wv.z, wv.w};
#pragma unroll
            for (int i = 0; i < 4; i++)
#pragma unroll
                for (int j = 0; j < 8; j++)
                    acc[i][j] = fmaf(wr[i], xr[j], acc[i][j]);
        }
        __syncthreads();
    }

    // BN + ReLU epilogue
    float val[4][8];
#pragma unroll
    for (int i = 0; i < 4; i++) {
        int r = rowb + i;
        float sc = gamma[r] * rsqrtf(var[r] + 1e-5f);
        float sh = fmaf(bias[r] - mean[r], sc, beta[r]);
#pragma unroll
        for (int j = 0; j < 8; j++)
            val[i][j] = fmaxf(fmaf(acc[i][j], sc, sh), 0.f);
    }

    if (!TRANS) {
#pragma unroll
        for (int i = 0; i < 4; i++) {
            float* o = &out[((size_t)b * COUT + rowb + i) * NN2 + n0 + colb];
            *(float4*)&o[0] = make_float4(val[i][0], val[i][1], val[i][2], val[i][3]);
            *(float4*)&o[4] = make_float4(val[i][4], val[i][5], val[i][6], val[i][7]);
        }
    } else {
#pragma unroll
        for (int j = 0; j < 8; j++) {
            float4 v = make_float4(val[0][j], val[1][j], val[2][j], val[3][j]);
            *(float4*)&out[((size_t)b * NN2 + n0 + colb + j) * COUT + rowb] = v;
        }
    }
}

// ---------------------------------------------------------------------------
// branchless top-3 insert (ascending d0<=d1<=d2); correct even if s>=d2
// ---------------------------------------------------------------------------
__device__ __forceinline__ void ins3(float s, int id,
                                     float& d0, float& d1, float& d2,
                                     int& i0, int& i1, int& i2)
{
    bool c2 = s < d2, c1 = s < d1, c0 = s < d0;
    float nd2 = c1 ? d1 : (c2 ? s : d2);
    int   ni2 = c1 ? i1 : (c2 ? id : i2);
    float nd1 = c0 ? d0 : (c1 ? s : d1);
    int   ni1 = c0 ? i0 : (c1 ? id : i1);
    d0 = c0 ? s : d0;  i0 = c0 ? id : i0;
    d1 = nd1; i1 = ni1;
    d2 = nd2; i2 = ni2;
}

// ---------------------------------------------------------------------------
// 3-NN + weighted interpolation.
// One thread per query point.  p2 staged in smem as SoA (x,y,z,|p|^2).
// Selection key s = |p2|^2 - 2*p1.p2 (constant |p1|^2 dropped in the scan,
// re-added for the weights -> identical to reference expansion trick).
// Per group of 4: 4 LDS.128 + 6 FFMA2 + 3 FMNMX + ONE branch; the taken
// path runs four fully-branchless inserts (no nested divergent regions).
// ---------------------------------------------------------------------------
__global__ void __launch_bounds__(256)
knn_interp_kernel(const float* __restrict__ p1,
                  const float* __restrict__ p2,
                  const float* __restrict__ ft,   // [B][N2][128]
                  float* __restrict__ out)        // [B][128][N1]
{
    __shared__ __align__(16) float sx[CHUNK];
    __shared__ __align__(16) float sy[CHUNK];
    __shared__ __align__(16) float sz[CHUNK];
    __shared__ __align__(16) float sw[CHUNK];

    const int t = threadIdx.x;
    const int b = blockIdx.y;
    const int n = blockIdx.x * 256 + t;

    const float* pp = p1 + ((size_t)b * NN1 + n) * 3;
    const float px = pp[0], py = pp[1], pz = pp[2];
    const ull MX2 = pack2(-2.f * px, -2.f * px);
    const ull MY2 = pack2(-2.f * py, -2.f * py);
    const ull MZ2 = pack2(-2.f * pz, -2.f * pz);
    const float c1 = px * px + py * py + pz * pz;

    const float INF = __int_as_float(0x7f800000);
    float d0 = INF, d1 = INF, d2 = INF;
    int   i0 = 0,   i1 = 0,   i2 = 0;

    const float* p2b = p2 + (size_t)b * NN2 * 3;

    for (int base = 0; base < NN2; base += CHUNK) {
        for (int k = t; k < CHUNK; k += 256) {
            const float* q = p2b + (size_t)(base + k) * 3;
            float x = q[0], y = q[1], z = q[2];
            sx[k] = x; sy[k] = y; sz[k] = z;
            sw[k] = fmaf(x, x, fmaf(y, y, z * z));
        }
        __syncthreads();

#pragma unroll 4
        for (int k = 0; k < CHUNK; k += 4) {
            F4U xq, yq, zq, wq;
            xq.f = *(const float4*)&sx[k];
            yq.f = *(const float4*)&sy[k];
            zq.f = *(const float4*)&sz[k];
            wq.f = *(const float4*)&sw[k];

            ull s01 = wq.u[0], s23 = wq.u[1];
            fma2(s01, xq.u[0], MX2, s01);
            fma2(s01, yq.u[0], MY2, s01);
            fma2(s01, zq.u[0], MZ2, s01);
            fma2(s23, xq.u[1], MX2, s23);
            fma2(s23, yq.u[1], MY2, s23);
            fma2(s23, zq.u[1], MZ2, s23);

            float2 a = unpack2(s01);
            float2 c = unpack2(s23);
            float m = fminf(fminf(a.x, a.y), fminf(c.x, c.y));
            if (m < d2) {
                int id = base + k;
                // single divergent region; all four inserts branchless
                ins3(a.x, id + 0, d0, d1, d2, i0, i1, i2);
                ins3(a.y, id + 1, d0, d1, d2, i0, i1, i2);
                ins3(c.x, id + 2, d0, d1, d2, i0, i1, i2);
                ins3(c.y, id + 3, d0, d1, d2, i0, i1, i2);
            }
        }
        __syncthreads();
    }

    // weights (reference: recip = 1/(d2 + 1e-8), normalized)
    float r0 = 1.f / (d0 + c1 + 1e-8f);
    float r1 = 1.f / (d1 + c1 + 1e-8f);
    float r2 = 1.f / (d2 + c1 + 1e-8f);
    float inv = 1.f / (r0 + r1 + r2);
    float w0 = r0 * inv, w1 = r1 * inv, w2 = r2 * inv;

    const float4* f0 = (const float4*)(ft + ((size_t)b * NN2 + i0) * COUT);
    const float4* f1 = (const float4*)(ft + ((size_t)b * NN2 + i1) * COUT);
    const float4* f2 = (const float4*)(ft + ((size_t)b * NN2 + i2) * COUT);
    float* ob = out + (size_t)b * COUT * NN1 + n;

#pragma unroll 4
    for (int j = 0; j < COUT / 4; j++) {
        float4 a = f0[j], c = f1[j], e = f2[j];
        float vx = w0 * a.x + w1 * c.x + w2 * e.x;
        float vy = w0 * a.y + w1 * c.y + w2 * e.y;
        float vz = w0 * a.z + w1 * c.z + w2 * e.z;
        float vw = w0 * a.w + w1 * c.w + w2 * e.w;
        ob[(size_t)(4 * j + 0) * NN1] = vx;
        ob[(size_t)(4 * j + 1) * NN1] = vy;
        ob[(size_t)(4 * j + 2) * NN1] = vz;
        ob[(size_t)(4 * j + 3) * NN1] = vw;
    }
}

// ---------------------------------------------------------------------------
extern "C" void kernel_launch(void* const* d_in, const int* in_sizes, int n_in,
                              void* d_out, int out_size)
{
    const float* p1 = (const float*)d_in[0];
    const float* p2 = (const float*)d_in[1];
    const float* f2 = (const float*)d_in[2];
    const float* W0 = (const float*)d_in[3];
    const float* b0 = (const float*)d_in[4];
    const float* g0 = (const float*)d_in[5];
    const float* be0 = (const float*)d_in[6];
    const float* m0 = (const float*)d_in[7];
    const float* v0 = (const float*)d_in[8];
    const float* W1 = (const float*)d_in[9];
    const float* b1 = (const float*)d_in[10];
    const float* g1 = (const float*)d_in[11];
    const float* be1 = (const float*)d_in[12];
    const float* m1 = (const float*)d_in[13];
    const float* v1 = (const float*)d_in[14];

    float* f0p = nullptr;
    float* ftp = nullptr;
    cudaGetSymbolAddress((void**)&f0p, g_f0);
    cudaGetSymbolAddress((void**)&ftp, g_ft);

    dim3 ggrid(NN2 / 64, BB);
    conv_bn_relu_kernel<256, false><<<ggrid, 256>>>(f2, W0, b0, g0, be0, m0, v0, f0p);
    conv_bn_relu_kernel<128, true ><<<ggrid, 256>>>(f0p, W1, b1, g1, be1, m1, v1, ftp);

    dim3 kgrid(NN1 / 256, BB);
    knn_interp_kernel<<<kgrid, 256>>>(p1, p2, ftp, (float*)d_out);
}

// round 12
// speedup vs baseline: 2.0126x; 1.2060x over previous
#include <cuda_runtime.h>
#include <cstdint>

#define BB    8
#define NN1   16384
#define NN2   4096
#define COUT  128
#define CHUNK 2048

typedef unsigned long long ull;

// Scratch (device globals; no allocation allowed)
__device__ float g_f0[(size_t)BB * COUT * NN2];      // layer0 output [B][128][N2]
__device__ float g_ft[(size_t)BB * NN2 * COUT];      // layer1 output transposed [B][N2][128]
__device__ float4 g_selw[(size_t)BB * NN1];          // per-query weights (w0,w1,w2,-)
__device__ int4   g_seli[(size_t)BB * NN1];          // per-query indices (i0,i1,i2,-)

// ---------------------------------------------------------------------------
// packed f32x2 helpers (kNN distance evaluation only)
// ---------------------------------------------------------------------------
__device__ __forceinline__ void fma2(ull& d, ull a, ull b, ull c) {
    asm("fma.rn.f32x2 %0, %1, %2, %3;" : "=l"(d) : "l"(a), "l"(b), "l"(c));
}
__device__ __forceinline__ ull pack2(float lo, float hi) {
    ull r; asm("mov.b64 %0, {%1, %2};" : "=l"(r) : "f"(lo), "f"(hi)); return r;
}
__device__ __forceinline__ float2 unpack2(ull v) {
    float2 r; asm("mov.b64 {%0, %1}, %2;" : "=f"(r.x), "=f"(r.y) : "l"(v)); return r;
}
union F4U { float4 f; ull u[2]; };

// ---------------------------------------------------------------------------
// Fused 1x1 conv + BN + ReLU.  X:[B][CIN][N2]  W:[128][CIN]
// Block = 256 threads computes a [128 cout x 64 n] tile.
// Thread tile: 4 cout x 8 n, scalar FFMA (32 FFMA / 3 LDS.128).
// TRANS=false: out[b][cout][n];  TRANS=true: out[b][n][cout]
// ---------------------------------------------------------------------------
template<int CIN, bool TRANS>
__global__ void __launch_bounds__(256)
conv_bn_relu_kernel(const float* __restrict__ X,
                    const float* __restrict__ W,
                    const float* __restrict__ bias,
                    const float* __restrict__ gamma,
                    const float* __restrict__ beta,
                    const float* __restrict__ mean,
                    const float* __restrict__ var,
                    float* __restrict__ out)
{
    __shared__ __align__(16) float Ws[32][132];   // [k][cout], padded
    __shared__ __align__(16) float Xs[32][68];    // [k][n],    padded

    const int t    = threadIdx.x;
    const int b    = blockIdx.y;
    const int n0   = blockIdx.x * 64;
    const int colb = (t & 7) * 8;     // 8 consecutive n columns
    const int rowb = (t >> 3) * 4;    // 4 consecutive cout rows

    float acc[4][8];
#pragma unroll
    for (int i = 0; i < 4; i++)
#pragma unroll
        for (int j = 0; j < 8; j++) acc[i][j] = 0.f;

    const float* Xb = X + (size_t)b * CIN * NN2;

    for (int c0 = 0; c0 < CIN; c0 += 32) {
        // stage W tile [32 k x 128 cout]
#pragma unroll
        for (int k = 0; k < 16; k++) {
            int idx = t + k * 256;
            int r = idx >> 5, c = idx & 31;
            Ws[c][r] = W[r * CIN + c0 + c];
        }
        // stage X tile [32 k x 64 n]
#pragma unroll
        for (int k = 0; k < 8; k++) {
            int idx = t + k * 256;
            int cc = idx >> 6, nn = idx & 63;
            Xs[cc][nn] = Xb[(size_t)(c0 + cc) * NN2 + n0 + nn];
        }
        __syncthreads();

#pragma unroll
        for (int cc = 0; cc < 32; cc++) {
            float4 xlo = *(const float4*)&Xs[cc][colb];
            float4 xhi = *(const float4*)&Xs[cc][colb + 4];
            float4 wv  = *(const float4*)&Ws[cc][rowb];
            float xr[8] = {xlo.x, xlo.y, xlo.z, xlo.w, xhi.x, xhi.y, xhi.z, xhi.w};
            float wr[4] = {wv.x, wv.y, wv.z, wv.w};
#pragma unroll
            for (int i = 0; i < 4; i++)
#pragma unroll
                for (int j = 0; j < 8; j++)
                    acc[i][j] = fmaf(wr[i], xr[j], acc[i][j]);
        }
        __syncthreads();
    }

    // BN + ReLU epilogue
    float val[4][8];
#pragma unroll
    for (int i = 0; i < 4; i++) {
        int r = rowb + i;
        float sc = gamma[r] * rsqrtf(var[r] + 1e-5f);
        float sh = fmaf(bias[r] - mean[r], sc, beta[r]);
#pragma unroll
        for (int j = 0; j < 8; j++)
            val[i][j] = fmaxf(fmaf(acc[i][j], sc, sh), 0.f);
    }

    if (!TRANS) {
#pragma unroll
        for (int i = 0; i < 4; i++) {
            float* o = &out[((size_t)b * COUT + rowb + i) * NN2 + n0 + colb];
            *(float4*)&o[0] = make_float4(val[i][0], val[i][1], val[i][2], val[i][3]);
            *(float4*)&o[4] = make_float4(val[i][4], val[i][5], val[i][6], val[i][7]);
        }
    } else {
#pragma unroll
        for (int j = 0; j < 8; j++) {
            float4 v = make_float4(val[0][j], val[1][j], val[2][j], val[3][j]);
            *(float4*)&out[((size_t)b * NN2 + n0 + colb + j) * COUT + rowb] = v;
        }
    }
}

// ---------------------------------------------------------------------------
// branchless top-3 insert (ascending d0<=d1<=d2); correct even if s>=d2
// ---------------------------------------------------------------------------
__device__ __forceinline__ void ins3(float s, int id,
                                     float& d0, float& d1, float& d2,
                                     int& i0, int& i1, int& i2)
{
    bool c2 = s < d2, c1 = s < d1, c0 = s < d0;
    float nd2 = c1 ? d1 : (c2 ? s : d2);
    int   ni2 = c1 ? i1 : (c2 ? id : i2);
    float nd1 = c0 ? d0 : (c1 ? s : d1);
    int   ni1 = c0 ? i0 : (c1 ? id : i1);
    d0 = c0 ? s : d0;  i0 = c0 ? id : i0;
    d1 = nd1; i1 = ni1;
    d2 = nd2; i2 = ni2;
}

// ---------------------------------------------------------------------------
// 3-NN selection: per query write 3 indices + normalized weights.
// (runs CONCURRENTLY with the conv chain — depends only on p1/p2)
// ---------------------------------------------------------------------------
__global__ void __launch_bounds__(256)
knn_select_kernel(const float* __restrict__ p1,
                  const float* __restrict__ p2,
                  float4* __restrict__ selw,
                  int4*   __restrict__ seli)
{
    __shared__ __align__(16) float sx[CHUNK];
    __shared__ __align__(16) float sy[CHUNK];
    __shared__ __align__(16) float sz[CHUNK];
    __shared__ __align__(16) float sw[CHUNK];

    const int t = threadIdx.x;
    const int b = blockIdx.y;
    const int n = blockIdx.x * 256 + t;

    const float* pp = p1 + ((size_t)b * NN1 + n) * 3;
    const float px = pp[0], py = pp[1], pz = pp[2];
    const ull MX2 = pack2(-2.f * px, -2.f * px);
    const ull MY2 = pack2(-2.f * py, -2.f * py);
    const ull MZ2 = pack2(-2.f * pz, -2.f * pz);
    const float c1 = px * px + py * py + pz * pz;

    const float INF = __int_as_float(0x7f800000);
    float d0 = INF, d1 = INF, d2 = INF;
    int   i0 = 0,   i1 = 0,   i2 = 0;

    const float* p2b = p2 + (size_t)b * NN2 * 3;

    for (int base = 0; base < NN2; base += CHUNK) {
        for (int k = t; k < CHUNK; k += 256) {
            const float* q = p2b + (size_t)(base + k) * 3;
            float x = q[0], y = q[1], z = q[2];
            sx[k] = x; sy[k] = y; sz[k] = z;
            sw[k] = fmaf(x, x, fmaf(y, y, z * z));
        }
        __syncthreads();

#pragma unroll 4
        for (int k = 0; k < CHUNK; k += 4) {
            F4U xq, yq, zq, wq;
            xq.f = *(const float4*)&sx[k];
            yq.f = *(const float4*)&sy[k];
            zq.f = *(const float4*)&sz[k];
            wq.f = *(const float4*)&sw[k];

            ull s01 = wq.u[0], s23 = wq.u[1];
            fma2(s01, xq.u[0], MX2, s01);
            fma2(s01, yq.u[0], MY2, s01);
            fma2(s01, zq.u[0], MZ2, s01);
            fma2(s23, xq.u[1], MX2, s23);
            fma2(s23, yq.u[1], MY2, s23);
            fma2(s23, zq.u[1], MZ2, s23);

            float2 a = unpack2(s01);
            float2 c = unpack2(s23);
            float m = fminf(fminf(a.x, a.y), fminf(c.x, c.y));
            if (m < d2) {
                int id = base + k;
                // single divergent region; all four inserts branchless
                ins3(a.x, id + 0, d0, d1, d2, i0, i1, i2);
                ins3(a.y, id + 1, d0, d1, d2, i0, i1, i2);
                ins3(c.x, id + 2, d0, d1, d2, i0, i1, i2);
                ins3(c.y, id + 3, d0, d1, d2, i0, i1, i2);
            }
        }
        __syncthreads();
    }

    // weights (reference: recip = 1/(d2 + 1e-8), normalized)
    float r0 = 1.f / (d0 + c1 + 1e-8f);
    float r1 = 1.f / (d1 + c1 + 1e-8f);
    float r2 = 1.f / (d2 + c1 + 1e-8f);
    float inv = 1.f / (r0 + r1 + r2);

    size_t qi = (size_t)b * NN1 + n;
    selw[qi] = make_float4(r0 * inv, r1 * inv, r2 * inv, 0.f);
    seli[qi] = make_int4(i0, i1, i2, 0);
}

// ---------------------------------------------------------------------------
// Gather + weighted sum: out[b][c][n1] = sum_k w_k * ft[b][idx_k][c]
// ---------------------------------------------------------------------------
__global__ void __launch_bounds__(256)
gather_kernel(const float* __restrict__ ft,      // [B][N2][128]
              const float4* __restrict__ selw,
              const int4*   __restrict__ seli,
              float* __restrict__ out)           // [B][128][N1]
{
    const int t = threadIdx.x;
    const int b = blockIdx.y;
    const int n = blockIdx.x * 256 + t;

    size_t qi = (size_t)b * NN1 + n;
    float4 w  = selw[qi];
    int4   id = seli[qi];

    const float4* f0 = (const float4*)(ft + ((size_t)b * NN2 + id.x) * COUT);
    const float4* f1 = (const float4*)(ft + ((size_t)b * NN2 + id.y) * COUT);
    const float4* f2 = (const float4*)(ft + ((size_t)b * NN2 + id.z) * COUT);
    float* ob = out + (size_t)b * COUT * NN1 + n;

#pragma unroll 4
    for (int j = 0; j < COUT / 4; j++) {
        float4 a = f0[j], c = f1[j], e = f2[j];
        float vx = w.x * a.x + w.y * c.x + w.z * e.x;
        float vy = w.x * a.y + w.y * c.y + w.z * e.y;
        float vz = w.x * a.z + w.y * c.z + w.z * e.z;
        float vw = w.x * a.w + w.y * c.w + w.z * e.w;
        ob[(size_t)(4 * j + 0) * NN1] = vx;
        ob[(size_t)(4 * j + 1) * NN1] = vy;
        ob[(size_t)(4 * j + 2) * NN1] = vz;
        ob[(size_t)(4 * j + 3) * NN1] = vw;
    }
}

// ---------------------------------------------------------------------------
extern "C" void kernel_launch(void* const* d_in, const int* in_sizes, int n_in,
                              void* d_out, int out_size)
{
    const float* p1 = (const float*)d_in[0];
    const float* p2 = (const float*)d_in[1];
    const float* f2 = (const float*)d_in[2];
    const float* W0 = (const float*)d_in[3];
    const float* b0 = (const float*)d_in[4];
    const float* g0 = (const float*)d_in[5];
    const float* be0 = (const float*)d_in[6];
    const float* m0 = (const float*)d_in[7];
    const float* v0 = (const float*)d_in[8];
    const float* W1 = (const float*)d_in[9];
    const float* b1 = (const float*)d_in[10];
    const float* g1 = (const float*)d_in[11];
    const float* be1 = (const float*)d_in[12];
    const float* m1 = (const float*)d_in[13];
    const float* v1 = (const float*)d_in[14];

    float*  f0p = nullptr;
    float*  ftp = nullptr;
    float4* swp = nullptr;
    int4*   sip = nullptr;
    cudaGetSymbolAddress((void**)&f0p, g_f0);
    cudaGetSymbolAddress((void**)&ftp, g_ft);
    cudaGetSymbolAddress((void**)&swp, g_selw);
    cudaGetSymbolAddress((void**)&sip, g_seli);

    // Fork a side stream for the kNN selection (independent of the convs).
    // Created fresh each call (a handful of calls total; host-side only, no
    // device allocation). Non-blocking so the legacy stream doesn't
    // implicitly serialize against it.
    cudaStream_t s2;
    cudaStreamCreateWithFlags(&s2, cudaStreamNonBlocking);
    cudaEvent_t evFork, evJoin;
    cudaEventCreateWithFlags(&evFork, cudaEventDisableTiming);
    cudaEventCreateWithFlags(&evJoin, cudaEventDisableTiming);

    cudaEventRecord(evFork, 0);
    cudaStreamWaitEvent(s2, evFork, 0);

    dim3 kgrid(NN1 / 256, BB);
    knn_select_kernel<<<kgrid, 256, 0, s2>>>(p1, p2, swp, sip);

    dim3 ggrid(NN2 / 64, BB);
    conv_bn_relu_kernel<256, false><<<ggrid, 256>>>(f2, W0, b0, g0, be0, m0, v0, f0p);
    conv_bn_relu_kernel<128, true ><<<ggrid, 256>>>(f0p, W1, b1, g1, be1, m1, v1, ftp);

    cudaEventRecord(evJoin, s2);
    cudaStreamWaitEvent(0, evJoin, 0);

    gather_kernel<<<kgrid, 256>>>(ftp, swp, sip, (float*)d_out);
}

// round 14
// speedup vs baseline: 2.3035x; 1.1445x over previous
#include <cuda_runtime.h>
#include <cstdint>

#define BB    8
#define NN1   16384
#define NN2   4096
#define COUT  128
#define CHUNK 2048

typedef unsigned long long ull;

// Scratch (device globals; no allocation allowed)
__device__ float g_f0[(size_t)BB * COUT * NN2];      // layer0 output [B][128][N2]
__device__ float g_ft[(size_t)BB * NN2 * COUT];      // layer1 output transposed [B][N2][128]
__device__ float4 g_selw[(size_t)BB * NN1];          // per-query weights (w0,w1,w2,-)
__device__ int4   g_seli[(size_t)BB * NN1];          // per-query indices (i0,i1,i2,-)

// ---------------------------------------------------------------------------
// packed f32x2 helpers (kNN distance evaluation only)
// ---------------------------------------------------------------------------
__device__ __forceinline__ void fma2(ull& d, ull a, ull b, ull c) {
    asm("fma.rn.f32x2 %0, %1, %2, %3;" : "=l"(d) : "l"(a), "l"(b), "l"(c));
}
__device__ __forceinline__ ull pack2(float lo, float hi) {
    ull r; asm("mov.b64 %0, {%1, %2};" : "=l"(r) : "f"(lo), "f"(hi)); return r;
}
__device__ __forceinline__ float2 unpack2(ull v) {
    float2 r; asm("mov.b64 {%0, %1}, %2;" : "=f"(r.x), "=f"(r.y) : "l"(v)); return r;
}
union F4U { float4 f; ull u[2]; };

// ---------------------------------------------------------------------------
// Fused 1x1 conv + BN + ReLU.  X:[B][CIN][N2]  W:[128][CIN]
// Block = 256 threads computes a [128 cout x 64 n] tile.
// Thread tile: 4 cout x 8 n, scalar FFMA (32 FFMA / 3 LDS.128).
// TRANS=false: out[b][cout][n];  TRANS=true: out[b][n][cout]
// ---------------------------------------------------------------------------
template<int CIN, bool TRANS>
__global__ void __launch_bounds__(256)
conv_bn_relu_kernel(const float* __restrict__ X,
                    const float* __restrict__ W,
                    const float* __restrict__ bias,
                    const float* __restrict__ gamma,
                    const float* __restrict__ beta,
                    const float* __restrict__ mean,
                    const float* __restrict__ var,
                    float* __restrict__ out)
{
    __shared__ __align__(16) float Ws[32][132];   // [k][cout], padded
    __shared__ __align__(16) float Xs[32][68];    // [k][n],    padded

    const int t    = threadIdx.x;
    const int b    = blockIdx.y;
    const int n0   = blockIdx.x * 64;
    const int colb = (t & 7) * 8;     // 8 consecutive n columns
    const int rowb = (t >> 3) * 4;    // 4 consecutive cout rows

    float acc[4][8];
#pragma unroll
    for (int i = 0; i < 4; i++)
#pragma unroll
        for (int j = 0; j < 8; j++) acc[i][j] = 0.f;

    const float* Xb = X + (size_t)b * CIN * NN2;

    for (int c0 = 0; c0 < CIN; c0 += 32) {
        // stage W tile [32 k x 128 cout]
#pragma unroll
        for (int k = 0; k < 16; k++) {
            int idx = t + k * 256;
            int r = idx >> 5, c = idx & 31;
            Ws[c][r] = W[r * CIN + c0 + c];
        }
        // stage X tile [32 k x 64 n]
#pragma unroll
        for (int k = 0; k < 8; k++) {
            int idx = t + k * 256;
            int cc = idx >> 6, nn = idx & 63;
            Xs[cc][nn] = Xb[(size_t)(c0 + cc) * NN2 + n0 + nn];
        }
        __syncthreads();

#pragma unroll
        for (int cc = 0; cc < 32; cc++) {
            float4 xlo = *(const float4*)&Xs[cc][colb];
            float4 xhi = *(const float4*)&Xs[cc][colb + 4];
            float4 wv  = *(const float4*)&Ws[cc][rowb];
            float xr[8] = {xlo.x, xlo.y, xlo.z, xlo.w, xhi.x, xhi.y, xhi.z, xhi.w};
            float wr[4] = {wv.x, wv.y, wv.z, wv.w};
#pragma unroll
            for (int i = 0; i < 4; i++)
#pragma unroll
                for (int j = 0; j < 8; j++)
                    acc[i][j] = fmaf(wr[i], xr[j], acc[i][j]);
        }
        __syncthreads();
    }

    // BN + ReLU epilogue
    float val[4][8];
#pragma unroll
    for (int i = 0; i < 4; i++) {
        int r = rowb + i;
        float sc = gamma[r] * rsqrtf(var[r] + 1e-5f);
        float sh = fmaf(bias[r] - mean[r], sc, beta[r]);
#pragma unroll
        for (int j = 0; j < 8; j++)
            val[i][j] = fmaxf(fmaf(acc[i][j], sc, sh), 0.f);
    }

    if (!TRANS) {
#pragma unroll
        for (int i = 0; i < 4; i++) {
            float* o = &out[((size_t)b * COUT + rowb + i) * NN2 + n0 + colb];
            *(float4*)&o[0] = make_float4(val[i][0], val[i][1], val[i][2], val[i][3]);
            *(float4*)&o[4] = make_float4(val[i][4], val[i][5], val[i][6], val[i][7]);
        }
    } else {
#pragma unroll
        for (int j = 0; j < 8; j++) {
            float4 v = make_float4(val[0][j], val[1][j], val[2][j], val[3][j]);
            *(float4*)&out[((size_t)b * NN2 + n0 + colb + j) * COUT + rowb] = v;
        }
    }
}

// ---------------------------------------------------------------------------
// branchless top-3 insert (ascending d0<=d1<=d2); correct even if s>=d2
// ---------------------------------------------------------------------------
__device__ __forceinline__ void ins3(float s, int id,
                                     float& d0, float& d1, float& d2,
                                     int& i0, int& i1, int& i2)
{
    bool c2 = s < d2, c1 = s < d1, c0 = s < d0;
    float nd2 = c1 ? d1 : (c2 ? s : d2);
    int   ni2 = c1 ? i1 : (c2 ? id : i2);
    float nd1 = c0 ? d0 : (c1 ? s : d1);
    int   ni1 = c0 ? i0 : (c1 ? id : i1);
    d0 = c0 ? s : d0;  i0 = c0 ? id : i0;
    d1 = nd1; i1 = ni1;
    d2 = nd2; i2 = ni2;
}

// ---------------------------------------------------------------------------
// 3-NN selection, TWO queries per thread (shared smem candidate reads).
// Block handles 512 queries: thread t -> n0+t and n0+256+t.
// ---------------------------------------------------------------------------
__global__ void __launch_bounds__(256)
knn_select_kernel(const float* __restrict__ p1,
                  const float* __restrict__ p2,
                  float4* __restrict__ selw,
                  int4*   __restrict__ seli)
{
    __shared__ __align__(16) float sx[CHUNK];
    __shared__ __align__(16) float sy[CHUNK];
    __shared__ __align__(16) float sz[CHUNK];
    __shared__ __align__(16) float sw[CHUNK];

    const int t = threadIdx.x;
    const int b = blockIdx.y;
    const int n0 = blockIdx.x * 512;
    const int nA = n0 + t;
    const int nB = n0 + 256 + t;

    const float* ppA = p1 + ((size_t)b * NN1 + nA) * 3;
    const float* ppB = p1 + ((size_t)b * NN1 + nB) * 3;
    const float axp = ppA[0], ayp = ppA[1], azp = ppA[2];
    const float bxp = ppB[0], byp = ppB[1], bzp = ppB[2];

    const ull MXA = pack2(-2.f * axp, -2.f * axp);
    const ull MYA = pack2(-2.f * ayp, -2.f * ayp);
    const ull MZA = pack2(-2.f * azp, -2.f * azp);
    const ull MXB = pack2(-2.f * bxp, -2.f * bxp);
    const ull MYB = pack2(-2.f * byp, -2.f * byp);
    const ull MZB = pack2(-2.f * bzp, -2.f * bzp);
    const float cA = axp * axp + ayp * ayp + azp * azp;
    const float cB = bxp * bxp + byp * byp + bzp * bzp;

    const float INF = __int_as_float(0x7f800000);
    float dA0 = INF, dA1 = INF, dA2 = INF;
    int   iA0 = 0,   iA1 = 0,   iA2 = 0;
    float dB0 = INF, dB1 = INF, dB2 = INF;
    int   iB0 = 0,   iB1 = 0,   iB2 = 0;

    const float* p2b = p2 + (size_t)b * NN2 * 3;

    for (int base = 0; base < NN2; base += CHUNK) {
        for (int k = t; k < CHUNK; k += 256) {
            const float* q = p2b + (size_t)(base + k) * 3;
            float x = q[0], y = q[1], z = q[2];
            sx[k] = x; sy[k] = y; sz[k] = z;
            sw[k] = fmaf(x, x, fmaf(y, y, z * z));
        }
        __syncthreads();

#pragma unroll 2
        for (int k = 0; k < CHUNK; k += 4) {
            F4U xq, yq, zq, wq;
            xq.f = *(const float4*)&sx[k];
            yq.f = *(const float4*)&sy[k];
            zq.f = *(const float4*)&sz[k];
            wq.f = *(const float4*)&sw[k];

            // query A distances
            ull a01 = wq.u[0], a23 = wq.u[1];
            fma2(a01, xq.u[0], MXA, a01);
            fma2(a01, yq.u[0], MYA, a01);
            fma2(a01, zq.u[0], MZA, a01);
            fma2(a23, xq.u[1], MXA, a23);
            fma2(a23, yq.u[1], MYA, a23);
            fma2(a23, zq.u[1], MZA, a23);
            // query B distances
            ull b01 = wq.u[0], b23 = wq.u[1];
            fma2(b01, xq.u[0], MXB, b01);
            fma2(b01, yq.u[0], MYB, b01);
            fma2(b01, zq.u[0], MZB, b01);
            fma2(b23, xq.u[1], MXB, b23);
            fma2(b23, yq.u[1], MYB, b23);
            fma2(b23, zq.u[1], MZB, b23);

            float2 aa = unpack2(a01);
            float2 ac = unpack2(a23);
            float2 ba = unpack2(b01);
            float2 bc = unpack2(b23);
            float mA = fminf(fminf(aa.x, aa.y), fminf(ac.x, ac.y));
            float mB = fminf(fminf(ba.x, ba.y), fminf(bc.x, bc.y));
            int id = base + k;
            if (mA < dA2) {
                ins3(aa.x, id + 0, dA0, dA1, dA2, iA0, iA1, iA2);
                ins3(aa.y, id + 1, dA0, dA1, dA2, iA0, iA1, iA2);
                ins3(ac.x, id + 2, dA0, dA1, dA2, iA0, iA1, iA2);
                ins3(ac.y, id + 3, dA0, dA1, dA2, iA0, iA1, iA2);
            }
            if (mB < dB2) {
                ins3(ba.x, id + 0, dB0, dB1, dB2, iB0, iB1, iB2);
                ins3(ba.y, id + 1, dB0, dB1, dB2, iB0, iB1, iB2);
                ins3(bc.x, id + 2, dB0, dB1, dB2, iB0, iB1, iB2);
                ins3(bc.y, id + 3, dB0, dB1, dB2, iB0, iB1, iB2);
            }
        }
        __syncthreads();
    }

    // weights (reference: recip = 1/(d2 + 1e-8), normalized)
    {
        float r0 = 1.f / (dA0 + cA + 1e-8f);
        float r1 = 1.f / (dA1 + cA + 1e-8f);
        float r2 = 1.f / (dA2 + cA + 1e-8f);
        float inv = 1.f / (r0 + r1 + r2);
        size_t qi = (size_t)b * NN1 + nA;
        selw[qi] = make_float4(r0 * inv, r1 * inv, r2 * inv, 0.f);
        seli[qi] = make_int4(iA0, iA1, iA2, 0);
    }
    {
        float r0 = 1.f / (dB0 + cB + 1e-8f);
        float r1 = 1.f / (dB1 + cB + 1e-8f);
        float r2 = 1.f / (dB2 + cB + 1e-8f);
        float inv = 1.f / (r0 + r1 + r2);
        size_t qi = (size_t)b * NN1 + nB;
        selw[qi] = make_float4(r0 * inv, r1 * inv, r2 * inv, 0.f);
        seli[qi] = make_int4(iB0, iB1, iB2, 0);
    }
}

// ---------------------------------------------------------------------------
// Gather + weighted sum, warp-per-query (coalesced 512B row reads).
// Block = 8 warps handles 32 queries; results staged in smem, written
// coalesced over n.  out[b][c][n1] = sum_k w_k * ft[b][idx_k][c]
// ---------------------------------------------------------------------------
__global__ void __launch_bounds__(256)
gather_kernel(const float* __restrict__ ft,      // [B][N2][128]
              const float4* __restrict__ selw,
              const int4*   __restrict__ seli,
              float* __restrict__ out)           // [B][128][N1]
{
    __shared__ float res[32][133];               // [query][channel], pad 133

    const int t  = threadIdx.x;
    const int b  = blockIdx.y;
    const int n0 = blockIdx.x * 32;
    const int w  = t >> 5, l = t & 31;

    const float* ftb = ft + (size_t)b * NN2 * COUT;

#pragma unroll
    for (int qq = 0; qq < 4; qq++) {
        int q = w * 4 + qq;                      // local query 0..31
        size_t qi = (size_t)b * NN1 + n0 + q;
        float4 wt = selw[qi];                    // broadcast
        int4   id = seli[qi];                    // broadcast
        const float4* f0 = (const float4*)(ftb + (size_t)id.x * COUT);
        const float4* f1 = (const float4*)(ftb + (size_t)id.y * COUT);
        const float4* f2 = (const float4*)(ftb + (size_t)id.z * COUT);
        float4 a = f0[l], c = f1[l], e = f2[l];  // coalesced 512B per row
        float vx = wt.x * a.x + wt.y * c.x + wt.z * e.x;
        float vy = wt.x * a.y + wt.y * c.y + wt.z * e.y;
        float vz = wt.x * a.z + wt.y * c.z + wt.z * e.z;
        float vw = wt.x * a.w + wt.y * c.w + wt.z * e.w;
        res[q][l * 4 + 0] = vx;
        res[q][l * 4 + 1] = vy;
        res[q][l * 4 + 2] = vz;
        res[q][l * 4 + 3] = vw;
    }
    __syncthreads();

    // write 128 c x 32 n tile, coalesced over n; LDS stride 133 (5 mod 32,
    // conflict-free across lanes)
#pragma unroll
    for (int it = 0; it < 16; it++) {
        int idx = t + it * 256;
        int c = idx >> 5, nn = idx & 31;
        out[((size_t)b * COUT + c) * NN1 + n0 + nn] = res[nn][c];
    }
}

// ---------------------------------------------------------------------------
extern "C" void kernel_launch(void* const* d_in, const int* in_sizes, int n_in,
                              void* d_out, int out_size)
{
    const float* p1 = (const float*)d_in[0];
    const float* p2 = (const float*)d_in[1];
    const float* f2 = (const float*)d_in[2];
    const float* W0 = (const float*)d_in[3];
    const float* b0 = (const float*)d_in[4];
    const float* g0 = (const float*)d_in[5];
    const float* be0 = (const float*)d_in[6];
    const float* m0 = (const float*)d_in[7];
    const float* v0 = (const float*)d_in[8];
    const float* W1 = (const float*)d_in[9];
    const float* b1 = (const float*)d_in[10];
    const float* g1 = (const float*)d_in[11];
    const float* be1 = (const float*)d_in[12];
    const float* m1 = (const float*)d_in[13];
    const float* v1 = (const float*)d_in[14];

    float*  f0p = nullptr;
    float*  ftp = nullptr;
    float4* swp = nullptr;
    int4*   sip = nullptr;
    cudaGetSymbolAddress((void**)&f0p, g_f0);
    cudaGetSymbolAddress((void**)&ftp, g_ft);
    cudaGetSymbolAddress((void**)&swp, g_selw);
    cudaGetSymbolAddress((void**)&sip, g_seli);

    // Fork a side stream for the kNN selection (independent of the convs).
    cudaStream_t s2;
    cudaStreamCreateWithFlags(&s2, cudaStreamNonBlocking);
    cudaEvent_t evFork, evJoin;
    cudaEventCreateWithFlags(&evFork, cudaEventDisableTiming);
    cudaEventCreateWithFlags(&evJoin, cudaEventDisableTiming);

    cudaEventRecord(evFork, 0);
    cudaStreamWaitEvent(s2, evFork, 0);

    dim3 kgrid(NN1 / 512, BB);
    knn_select_kernel<<<kgrid, 256, 0, s2>>>(p1, p2, swp, sip);

    dim3 ggrid(NN2 / 64, BB);
    conv_bn_relu_kernel<256, false><<<ggrid, 256>>>(f2, W0, b0, g0, be0, m0, v0, f0p);
    conv_bn_relu_kernel<128, true ><<<ggrid, 256>>>(f0p, W1, b1, g1, be1, m1, v1, ftp);

    cudaEventRecord(evJoin, s2);
    cudaStreamWaitEvent(0, evJoin, 0);

    dim3 grgrid(NN1 / 32, BB);
    gather_kernel<<<grgrid, 256>>>(ftp, swp, sip, (float*)d_out);
}